// round 2
// baseline (speedup 1.0000x reference)
#include <cuda_runtime.h>
#include <cuda_bf16.h>
#include <cstdint>

// ---------------------------------------------------------------------------
// Problem constants
// ---------------------------------------------------------------------------
constexpr int BATCH = 8;
constexpr int CDIM  = 512;
constexpr int SDIM  = 1024;            // 32*32 tokens per batch
constexpr int MTOT  = BATCH * SDIM;    // 8192 token rows
constexpr int HD    = 64;              // head dim of the reshaped groups
constexpr int NGROUPS = 64;            // B * NUM_HEADS
constexpr int GROUP_ELEMS = SDIM * HD; // 65536 floats per group

// Scratch (device-global; allocation inside kernel_launch is forbidden)
__device__ float g_Q[MTOT * CDIM];
__device__ float g_K[MTOT * CDIM];
__device__ float g_V[MTOT * CDIM];
__device__ float g_O[MTOT * CDIM];

// ---------------------------------------------------------------------------
// mma.sync m16n8k16 bf16 helper (fp32 accumulate)
// ---------------------------------------------------------------------------
__device__ __forceinline__ void mma16816(float c[4], const uint32_t a[4], const uint32_t b[2])
{
    asm volatile(
        "mma.sync.aligned.m16n8k16.row.col.f32.bf16.bf16.f32 "
        "{%0,%1,%2,%3}, {%4,%5,%6,%7}, {%8,%9}, {%0,%1,%2,%3};\n"
        : "+f"(c[0]), "+f"(c[1]), "+f"(c[2]), "+f"(c[3])
        : "r"(a[0]), "r"(a[1]), "r"(a[2]), "r"(a[3]),
          "r"(b[0]), "r"(b[1]));
}

// ---------------------------------------------------------------------------
// Kernel 1: fused QKV GEMM.  Out[s, o] = sum_c t[s,c] * W[o,c] + bias[o]
//   t[s,c] = x[b, c, p]  (s = b*1024 + p)  -- transpose folded into the load.
//   bf16 hi/lo split, 3 MMAs (hh + hl + lh) for ~fp32 accuracy.
//   grid: (N/128, M/128, 3)   block: 256 threads (8 warps, 2x4, 64x32 each)
// ---------------------------------------------------------------------------
__global__ __launch_bounds__(256, 1) void qkv_gemm_kernel(
    const float* __restrict__ x,
    const float* __restrict__ Wq, const float* __restrict__ bq,
    const float* __restrict__ Wk, const float* __restrict__ bk,
    const float* __restrict__ Wv, const float* __restrict__ bv)
{
    constexpr int BM = 128, BN = 128, BK = 32;
    constexpr int PAD = 8;
    __shared__ __nv_bfloat16 As[2][BM][BK + PAD];   // [hi/lo][m][k]
    __shared__ __nv_bfloat16 Bs[2][BN][BK + PAD];   // [hi/lo][n][k]

    const int mat = blockIdx.z;
    const float* W    = (mat == 0) ? Wq : (mat == 1) ? Wk : Wv;
    const float* bias = (mat == 0) ? bq : (mat == 1) ? bk : bv;
    float* Out        = (mat == 0) ? g_Q : (mat == 1) ? g_K : g_V;

    const int m0 = blockIdx.y * BM;
    const int n0 = blockIdx.x * BN;
    const int b  = m0 >> 10;       // BM=128 divides SDIM=1024: tile stays in one batch
    const int p0 = m0 & 1023;

    const int tid  = threadIdx.x;
    const int warp = tid >> 5;
    const int lane = tid & 31;
    const int wm = (warp >> 2) * 64;
    const int wn = (warp & 3) * 32;
    const int gr = lane >> 2;
    const int t4 = lane & 3;

    float acc[4][4][4];
    #pragma unroll
    for (int i = 0; i < 4; i++)
        #pragma unroll
        for (int j = 0; j < 4; j++)
            #pragma unroll
            for (int r = 0; r < 4; r++) acc[i][j][r] = 0.f;

    for (int k0 = 0; k0 < CDIM; k0 += BK) {
        // A tile: 128 tokens x 32 channels, coalesced along p
        #pragma unroll
        for (int i = tid; i < BM * BK; i += 256) {
            int pp = i & (BM - 1);
            int kc = i >> 7;
            float v = x[((size_t)b * CDIM + (k0 + kc)) * SDIM + (p0 + pp)];
            __nv_bfloat16 h = __float2bfloat16(v);
            As[0][pp][kc] = h;
            As[1][pp][kc] = __float2bfloat16(v - __bfloat162float(h));
        }
        // B tile: 128 out-channels x 32 in-channels, coalesced along c
        #pragma unroll
        for (int i = tid; i < BN * BK; i += 256) {
            int kc = i & (BK - 1);
            int nn = i >> 5;
            float v = W[(size_t)(n0 + nn) * CDIM + (k0 + kc)];
            __nv_bfloat16 h = __float2bfloat16(v);
            Bs[0][nn][kc] = h;
            Bs[1][nn][kc] = __float2bfloat16(v - __bfloat162float(h));
        }
        __syncthreads();

        #pragma unroll
        for (int ks = 0; ks < BK; ks += 16) {
            uint32_t a[4][2][4];
            #pragma unroll
            for (int mi = 0; mi < 4; mi++) {
                int r = wm + mi * 16 + gr;
                #pragma unroll
                for (int s = 0; s < 2; s++) {
                    a[mi][s][0] = *(const uint32_t*)&As[s][r    ][ks + 2 * t4];
                    a[mi][s][1] = *(const uint32_t*)&As[s][r + 8][ks + 2 * t4];
                    a[mi][s][2] = *(const uint32_t*)&As[s][r    ][ks + 2 * t4 + 8];
                    a[mi][s][3] = *(const uint32_t*)&As[s][r + 8][ks + 2 * t4 + 8];
                }
            }
            uint32_t bb[4][2][2];
            #pragma unroll
            for (int ni = 0; ni < 4; ni++) {
                int n = wn + ni * 8 + gr;
                #pragma unroll
                for (int s = 0; s < 2; s++) {
                    bb[ni][s][0] = *(const uint32_t*)&Bs[s][n][ks + 2 * t4];
                    bb[ni][s][1] = *(const uint32_t*)&Bs[s][n][ks + 2 * t4 + 8];
                }
            }
            #pragma unroll
            for (int mi = 0; mi < 4; mi++)
                #pragma unroll
                for (int ni = 0; ni < 4; ni++) {
                    mma16816(acc[mi][ni], a[mi][0], bb[ni][0]);  // hi*hi
                    mma16816(acc[mi][ni], a[mi][0], bb[ni][1]);  // hi*lo
                    mma16816(acc[mi][ni], a[mi][1], bb[ni][0]);  // lo*hi
                }
        }
        __syncthreads();
    }

    // Epilogue: bias add, store fp32 row-major [M, C]
    #pragma unroll
    for (int mi = 0; mi < 4; mi++) {
        int r0 = m0 + wm + mi * 16 + gr;
        #pragma unroll
        for (int ni = 0; ni < 4; ni++) {
            int c = n0 + wn + ni * 8 + 2 * t4;
            float b0v = bias[c], b1v = bias[c + 1];
            Out[(size_t)r0 * CDIM + c]           = acc[mi][ni][0] + b0v;
            Out[(size_t)r0 * CDIM + c + 1]       = acc[mi][ni][1] + b1v;
            Out[(size_t)(r0 + 8) * CDIM + c]     = acc[mi][ni][2] + b0v;
            Out[(size_t)(r0 + 8) * CDIM + c + 1] = acc[mi][ni][3] + b1v;
        }
    }
}

// ---------------------------------------------------------------------------
// Kernel 2: flash attention over 64 groups of [1024, 64].
//   grid: (8 query-tiles, 64 groups)  block: 256 threads (8 warps x 16 rows)
// ---------------------------------------------------------------------------
constexpr int ATT_BM = 128;
constexpr int ATT_BN = 128;
constexpr int KS_STRIDE = HD + 8;                         // 72
constexpr int KS_BYTES  = 2 * ATT_BN * KS_STRIDE * 2;     // 36864
constexpr int VT_STRIDE = ATT_BN + 8;                     // 136
constexpr int VT_BYTES  = 2 * HD * VT_STRIDE * 2;         // 34816
constexpr int P_STRIDE  = ATT_BN + 8;                     // 136
constexpr int P_WARP_ELE = 2 * 16 * P_STRIDE;             // per warp, elements
constexpr int P_BYTES    = 8 * P_WARP_ELE * 2;            // 69632
constexpr int ATT_SMEM   = KS_BYTES + VT_BYTES + P_BYTES; // 141312 bytes

__global__ __launch_bounds__(256, 1) void attn_kernel()
{
    extern __shared__ char smem_raw[];
    typedef __nv_bfloat16 bf;
    bf (*Ks)[ATT_BN][KS_STRIDE] = (bf (*)[ATT_BN][KS_STRIDE])(smem_raw);
    bf (*VsT)[HD][VT_STRIDE]    = (bf (*)[HD][VT_STRIDE])(smem_raw + KS_BYTES);
    bf* Pbase                   = (bf*)(smem_raw + KS_BYTES + VT_BYTES);
    bf (*Qs)[ATT_BM][KS_STRIDE] = (bf (*)[ATT_BM][KS_STRIDE])(Pbase);  // alias (Q used before P)

    const int g  = blockIdx.y;
    const int qb = blockIdx.x;
    const float* Qg = g_Q + (size_t)g * GROUP_ELEMS;
    const float* Kg = g_K + (size_t)g * GROUP_ELEMS;
    const float* Vg = g_V + (size_t)g * GROUP_ELEMS;
    float*       Og = g_O + (size_t)g * GROUP_ELEMS;

    const int tid = threadIdx.x, warp = tid >> 5, lane = tid & 31;
    const int gr = lane >> 2, t4 = lane & 3;

    // --- load Q tile (pre-scaled by 1/sqrt(hd)=0.125), split to bf16 hi/lo ---
    #pragma unroll
    for (int i = tid; i < ATT_BM * HD; i += 256) {
        int d = i & 63, r = i >> 6;
        float v = Qg[qb * ATT_BM * HD + i] * 0.125f;
        bf h = __float2bfloat16(v);
        Qs[0][r][d] = h;
        Qs[1][r][d] = __float2bfloat16(v - __bfloat162float(h));
    }
    __syncthreads();

    // --- build Q register fragments (warp owns rows [warp*16, warp*16+16)) ---
    uint32_t qa[4][2][4];
    {
        int r = warp * 16 + gr;
        #pragma unroll
        for (int ks = 0; ks < 4; ks++)
            #pragma unroll
            for (int s = 0; s < 2; s++) {
                qa[ks][s][0] = *(const uint32_t*)&Qs[s][r    ][ks * 16 + 2 * t4];
                qa[ks][s][1] = *(const uint32_t*)&Qs[s][r + 8][ks * 16 + 2 * t4];
                qa[ks][s][2] = *(const uint32_t*)&Qs[s][r    ][ks * 16 + 2 * t4 + 8];
                qa[ks][s][3] = *(const uint32_t*)&Qs[s][r + 8][ks * 16 + 2 * t4 + 8];
            }
    }
    __syncthreads();   // Q region may now be reused as P

    float mrow[2] = {-1e30f, -1e30f};
    float lrow[2] = {0.f, 0.f};
    float o[8][4];
    #pragma unroll
    for (int i = 0; i < 8; i++)
        #pragma unroll
        for (int j = 0; j < 4; j++) o[i][j] = 0.f;

    bf* Pw = Pbase + warp * P_WARP_ELE;   // [split][16 rows][P_STRIDE]

    for (int kt = 0; kt < SDIM / ATT_BN; kt++) {
        // --- load K and V tiles (V transposed for the row.col second MMA) ---
        #pragma unroll
        for (int i = tid; i < ATT_BN * HD; i += 256) {
            int d = i & 63, r = i >> 6;
            float kv = Kg[kt * ATT_BN * HD + i];
            bf h = __float2bfloat16(kv);
            Ks[0][r][d] = h;
            Ks[1][r][d] = __float2bfloat16(kv - __bfloat162float(h));
            float vv = Vg[kt * ATT_BN * HD + i];
            bf hv = __float2bfloat16(vv);
            VsT[0][d][r] = hv;
            VsT[1][d][r] = __float2bfloat16(vv - __bfloat162float(hv));
        }
        __syncthreads();

        // --- scores: S = (Q*scale) @ K^T  (bf16x3) ---
        float sc[16][4];
        #pragma unroll
        for (int ni = 0; ni < 16; ni++) {
            float c[4] = {0.f, 0.f, 0.f, 0.f};
            int n = ni * 8 + gr;    // kv row index
            #pragma unroll
            for (int ks = 0; ks < 4; ks++) {
                uint32_t bh[2] = { *(const uint32_t*)&Ks[0][n][ks * 16 + 2 * t4],
                                   *(const uint32_t*)&Ks[0][n][ks * 16 + 2 * t4 + 8] };
                uint32_t bl[2] = { *(const uint32_t*)&Ks[1][n][ks * 16 + 2 * t4],
                                   *(const uint32_t*)&Ks[1][n][ks * 16 + 2 * t4 + 8] };
                mma16816(c, qa[ks][0], bh);
                mma16816(c, qa[ks][0], bl);
                mma16816(c, qa[ks][1], bh);
            }
            sc[ni][0] = c[0]; sc[ni][1] = c[1]; sc[ni][2] = c[2]; sc[ni][3] = c[3];
        }

        // --- online softmax update (two rows per thread: gr and gr+8) ---
        float tm0 = -1e30f, tm1 = -1e30f;
        #pragma unroll
        for (int ni = 0; ni < 16; ni++) {
            tm0 = fmaxf(tm0, fmaxf(sc[ni][0], sc[ni][1]));
            tm1 = fmaxf(tm1, fmaxf(sc[ni][2], sc[ni][3]));
        }
        tm0 = fmaxf(tm0, __shfl_xor_sync(0xffffffffu, tm0, 1));
        tm0 = fmaxf(tm0, __shfl_xor_sync(0xffffffffu, tm0, 2));
        tm1 = fmaxf(tm1, __shfl_xor_sync(0xffffffffu, tm1, 1));
        tm1 = fmaxf(tm1, __shfl_xor_sync(0xffffffffu, tm1, 2));

        float mn0 = fmaxf(mrow[0], tm0), mn1 = fmaxf(mrow[1], tm1);
        float alpha0 = __expf(mrow[0] - mn0), alpha1 = __expf(mrow[1] - mn1);

        float rs0 = 0.f, rs1 = 0.f;
        #pragma unroll
        for (int ni = 0; ni < 16; ni++) {
            float p0 = __expf(sc[ni][0] - mn0);
            float p1 = __expf(sc[ni][1] - mn0);
            float p2 = __expf(sc[ni][2] - mn1);
            float p3 = __expf(sc[ni][3] - mn1);
            rs0 += p0 + p1;
            rs1 += p2 + p3;
            int col = ni * 8 + 2 * t4;
            bf h0 = __float2bfloat16(p0), h1 = __float2bfloat16(p1);
            bf h2 = __float2bfloat16(p2), h3 = __float2bfloat16(p3);
            // hi split: rows gr and gr+8 (plain indices — the round-1 bug was here)
            *(__nv_bfloat162*)&Pw[(gr     ) * P_STRIDE + col] = __nv_bfloat162(h0, h1);
            *(__nv_bfloat162*)&Pw[(gr + 8 ) * P_STRIDE + col] = __nv_bfloat162(h2, h3);
            bf l0 = __float2bfloat16(p0 - __bfloat162float(h0));
            bf l1 = __float2bfloat16(p1 - __bfloat162float(h1));
            bf l2 = __float2bfloat16(p2 - __bfloat162float(h2));
            bf l3 = __float2bfloat16(p3 - __bfloat162float(h3));
            // lo split: rows 16+gr and 16+gr+8
            *(__nv_bfloat162*)&Pw[(16 + gr    ) * P_STRIDE + col] = __nv_bfloat162(l0, l1);
            *(__nv_bfloat162*)&Pw[(16 + gr + 8) * P_STRIDE + col] = __nv_bfloat162(l2, l3);
        }
        rs0 += __shfl_xor_sync(0xffffffffu, rs0, 1);
        rs0 += __shfl_xor_sync(0xffffffffu, rs0, 2);
        rs1 += __shfl_xor_sync(0xffffffffu, rs1, 1);
        rs1 += __shfl_xor_sync(0xffffffffu, rs1, 2);

        lrow[0] = lrow[0] * alpha0 + rs0;
        lrow[1] = lrow[1] * alpha1 + rs1;
        mrow[0] = mn0; mrow[1] = mn1;
        #pragma unroll
        for (int ni2 = 0; ni2 < 8; ni2++) {
            o[ni2][0] *= alpha0; o[ni2][1] *= alpha0;
            o[ni2][2] *= alpha1; o[ni2][3] *= alpha1;
        }
        __syncwarp();   // P is warp-private; order writes before reads

        // --- O += P @ V  (bf16x3) ---
        #pragma unroll
        for (int ks = 0; ks < 8; ks++) {
            uint32_t pa[2][4];
            #pragma unroll
            for (int s = 0; s < 2; s++) {
                pa[s][0] = *(const uint32_t*)&Pw[(s * 16 + gr    ) * P_STRIDE + ks * 16 + 2 * t4];
                pa[s][1] = *(const uint32_t*)&Pw[(s * 16 + gr + 8) * P_STRIDE + ks * 16 + 2 * t4];
                pa[s][2] = *(const uint32_t*)&Pw[(s * 16 + gr    ) * P_STRIDE + ks * 16 + 2 * t4 + 8];
                pa[s][3] = *(const uint32_t*)&Pw[(s * 16 + gr + 8) * P_STRIDE + ks * 16 + 2 * t4 + 8];
            }
            #pragma unroll
            for (int ni2 = 0; ni2 < 8; ni2++) {
                int n = ni2 * 8 + gr;   // d index
                uint32_t bh[2] = { *(const uint32_t*)&VsT[0][n][ks * 16 + 2 * t4],
                                   *(const uint32_t*)&VsT[0][n][ks * 16 + 2 * t4 + 8] };
                uint32_t bl[2] = { *(const uint32_t*)&VsT[1][n][ks * 16 + 2 * t4],
                                   *(const uint32_t*)&VsT[1][n][ks * 16 + 2 * t4 + 8] };
                mma16816(o[ni2], pa[0], bh);
                mma16816(o[ni2], pa[0], bl);
                mma16816(o[ni2], pa[1], bh);
            }
        }
        __syncthreads();   // before next K/V tile overwrite
    }

    // --- epilogue: normalize and store (group layout; transpose kernel finishes) ---
    float inv0 = 1.f / lrow[0], inv1 = 1.f / lrow[1];
    int r = qb * ATT_BM + warp * 16 + gr;
    #pragma unroll
    for (int ni2 = 0; ni2 < 8; ni2++) {
        int c = ni2 * 8 + 2 * t4;
        Og[(size_t)r * HD + c]           = o[ni2][0] * inv0;
        Og[(size_t)r * HD + c + 1]       = o[ni2][1] * inv0;
        Og[(size_t)(r + 8) * HD + c]     = o[ni2][2] * inv1;
        Og[(size_t)(r + 8) * HD + c + 1] = o[ni2][3] * inv1;
    }
}

// ---------------------------------------------------------------------------
// Kernel 3: per-batch transpose.  out[b, ch, p] = O_flat[b, p, ch]
// ---------------------------------------------------------------------------
__global__ void transpose_kernel(float* __restrict__ out)
{
    __shared__ float tile[32][33];
    const int b   = blockIdx.z;
    const int ch0 = blockIdx.x * 32;
    const int p0  = blockIdx.y * 32;
    const float* in = g_O + (size_t)b * SDIM * CDIM;
    float* o        = out + (size_t)b * SDIM * CDIM;
    const int tx = threadIdx.x, ty = threadIdx.y;
    #pragma unroll
    for (int i = 0; i < 32; i += 8)
        tile[ty + i][tx] = in[(size_t)(p0 + ty + i) * CDIM + ch0 + tx];
    __syncthreads();
    #pragma unroll
    for (int i = 0; i < 32; i += 8)
        o[(size_t)(ch0 + ty + i) * SDIM + p0 + tx] = tile[tx][ty + i];
}

// ---------------------------------------------------------------------------
// Launch
// ---------------------------------------------------------------------------
extern "C" void kernel_launch(void* const* d_in, const int* in_sizes, int n_in,
                              void* d_out, int out_size)
{
    (void)in_sizes; (void)n_in; (void)out_size;
    const float* x  = (const float*)d_in[0];
    const float* Wq = (const float*)d_in[1];
    const float* bq = (const float*)d_in[2];
    const float* Wk = (const float*)d_in[3];
    const float* bk = (const float*)d_in[4];
    const float* Wv = (const float*)d_in[5];
    const float* bv = (const float*)d_in[6];
    float* out = (float*)d_out;

    qkv_gemm_kernel<<<dim3(CDIM / 128, MTOT / 128, 3), 256>>>(x, Wq, bq, Wk, bk, Wv, bv);

    cudaFuncSetAttribute(attn_kernel, cudaFuncAttributeMaxDynamicSharedMemorySize, ATT_SMEM);
    attn_kernel<<<dim3(SDIM / ATT_BM, NGROUPS), 256, ATT_SMEM>>>();

    transpose_kernel<<<dim3(CDIM / 32, SDIM / 32, BATCH), dim3(32, 8)>>>(out);
}

// round 3
// speedup vs baseline: 1.5209x; 1.5209x over previous
#include <cuda_runtime.h>
#include <cuda_bf16.h>
#include <cstdint>

typedef __nv_bfloat16 bf;

constexpr int BATCH = 8;
constexpr int CDIM  = 512;
constexpr int SDIM  = 1024;
constexpr int MTOT  = BATCH * SDIM;    // 8192
constexpr int HD    = 64;
constexpr int NGROUPS = 64;
constexpr int GROUP_ELEMS = SDIM * HD; // 65536

// bf16 hi/lo global scratch
__device__ bf g_Ah[MTOT * CDIM];
__device__ bf g_Al[MTOT * CDIM];
__device__ bf g_Wh[3 * CDIM * CDIM];
__device__ bf g_Wl[3 * CDIM * CDIM];
__device__ bf g_Qh[MTOT * CDIM];
__device__ bf g_Ql[MTOT * CDIM];
__device__ bf g_Kh[MTOT * CDIM];
__device__ bf g_Kl[MTOT * CDIM];
__device__ bf g_Vh[MTOT * CDIM];
__device__ bf g_Vl[MTOT * CDIM];

// ---------------------------------------------------------------------------
// helpers
// ---------------------------------------------------------------------------
__device__ __forceinline__ void mma16816(float c[4], const uint32_t a[4], uint32_t b0, uint32_t b1)
{
    asm volatile(
        "mma.sync.aligned.m16n8k16.row.col.f32.bf16.bf16.f32 "
        "{%0,%1,%2,%3}, {%4,%5,%6,%7}, {%8,%9}, {%0,%1,%2,%3};\n"
        : "+f"(c[0]), "+f"(c[1]), "+f"(c[2]), "+f"(c[3])
        : "r"(a[0]), "r"(a[1]), "r"(a[2]), "r"(a[3]), "r"(b0), "r"(b1));
}
__device__ __forceinline__ void ldsm4(uint32_t& r0, uint32_t& r1, uint32_t& r2, uint32_t& r3, uint32_t a)
{
    asm volatile("ldmatrix.sync.aligned.m8n8.x4.shared.b16 {%0,%1,%2,%3}, [%4];"
                 : "=r"(r0), "=r"(r1), "=r"(r2), "=r"(r3) : "r"(a));
}
__device__ __forceinline__ void ldsm4t(uint32_t& r0, uint32_t& r1, uint32_t& r2, uint32_t& r3, uint32_t a)
{
    asm volatile("ldmatrix.sync.aligned.m8n8.x4.trans.shared.b16 {%0,%1,%2,%3}, [%4];"
                 : "=r"(r0), "=r"(r1), "=r"(r2), "=r"(r3) : "r"(a));
}
__device__ __forceinline__ void cp16(uint32_t dst, const void* src)
{
    asm volatile("cp.async.cg.shared.global [%0], [%1], 16;" :: "r"(dst), "l"(src));
}
__device__ __forceinline__ void cp_commit() { asm volatile("cp.async.commit_group;"); }
__device__ __forceinline__ void cp_wait1()  { asm volatile("cp.async.wait_group 1;"); }
__device__ __forceinline__ void cp_wait0()  { asm volatile("cp.async.wait_group 0;"); }

__device__ __forceinline__ uint32_t pack2(bf a, bf b)
{
    __nv_bfloat162 t(a, b);
    return *reinterpret_cast<uint32_t*>(&t);
}

// smem tile geometry: rows of 64 bf16 padded to 72 elems (144 B, 16B aligned)
constexpr int TSTRIDE   = 72;
constexpr int ARR_BYTES = 128 * TSTRIDE * 2;     // 18432
constexpr int STG_BYTES = 4 * ARR_BYTES;         // 73728 (Kh,Kl,Vh,Vl) or (Ah,Al,Bh,Bl)
constexpr int SMEM_TOT  = 2 * STG_BYTES;         // 147456

// ---------------------------------------------------------------------------
// Prep kernels: fp32 -> bf16 hi/lo
// ---------------------------------------------------------------------------
__global__ void prep_x_kernel(const float* __restrict__ x)
{
    __shared__ float tile[32][33];
    const int b  = blockIdx.z;
    const int c0 = blockIdx.x * 32;
    const int p0 = blockIdx.y * 32;
    const int tx = threadIdx.x, ty = threadIdx.y;
    #pragma unroll
    for (int i = 0; i < 32; i += 8)
        tile[ty + i][tx] = x[((size_t)b * CDIM + c0 + ty + i) * SDIM + p0 + tx];
    __syncthreads();
    #pragma unroll
    for (int i = 0; i < 32; i += 8) {
        int s = b * SDIM + p0 + ty + i;
        int c = c0 + tx;
        float v = tile[tx][ty + i];
        bf h = __float2bfloat16(v);
        g_Ah[(size_t)s * CDIM + c] = h;
        g_Al[(size_t)s * CDIM + c] = __float2bfloat16(v - __bfloat162float(h));
    }
}

__global__ void prep_w_kernel(const float* __restrict__ Wq,
                              const float* __restrict__ Wk,
                              const float* __restrict__ Wv)
{
    const int mat = blockIdx.y;
    const float* W = (mat == 0) ? Wq : (mat == 1) ? Wk : Wv;
    int base = (blockIdx.x * 256 + threadIdx.x) * 4;
    size_t o = (size_t)mat * CDIM * CDIM;
    #pragma unroll
    for (int e = 0; e < 4; e++) {
        float v = W[base + e];
        bf h = __float2bfloat16(v);
        g_Wh[o + base + e] = h;
        g_Wl[o + base + e] = __float2bfloat16(v - __bfloat162float(h));
    }
}

// ---------------------------------------------------------------------------
// Kernel 1: QKV GEMM, pure bf16, cp.async double buffered, ldmatrix frags.
//   grid (4, 64, 3), block 256 (8 warps, 2x4 layout, 64x32 warp tiles)
//   Epilogue writes bf16 hi/lo (Q scaled by 0.125).
// ---------------------------------------------------------------------------
__global__ __launch_bounds__(256, 1) void qkv_gemm_kernel(
    const float* __restrict__ bq, const float* __restrict__ bk, const float* __restrict__ bv)
{
    extern __shared__ char smem[];
    const uint32_t sbase = (uint32_t)__cvta_generic_to_shared(smem);

    const int mat = blockIdx.z;
    const float* bias = (mat == 0) ? bq : (mat == 1) ? bk : bv;
    const float scale = (mat == 0) ? 0.125f : 1.0f;
    bf* outh = (mat == 0) ? g_Qh : (mat == 1) ? g_Kh : g_Vh;
    bf* outl = (mat == 0) ? g_Ql : (mat == 1) ? g_Kl : g_Vl;

    const int m0 = blockIdx.y * 128;
    const int n0 = blockIdx.x * 128;
    const int tid = threadIdx.x, warp = tid >> 5, lane = tid & 31;
    const int wm = (warp >> 2) * 64, wn = (warp & 3) * 32;
    const int gr = lane >> 2, t4 = lane & 3;
    const int j = lane >> 3, lr = lane & 7;
    const int rowA = (j & 1) * 8 + lr, colA = (j >> 1) * 8;   // A-frag lane pattern
    const int rowB = (j >> 1) * 8 + lr, colB = (j & 1) * 8;   // B-frag lane pattern

    const bf* srcs[4] = { g_Ah, g_Al, g_Wh + (size_t)mat * CDIM * CDIM, g_Wl + (size_t)mat * CDIM * CDIM };

    auto issue = [&](int kt) {
        int k0 = kt * 64;
        uint32_t st = sbase + (kt & 1) * STG_BYTES;
        #pragma unroll
        for (int arr = 0; arr < 4; arr++) {
            int rbase = (arr < 2) ? m0 : n0;
            #pragma unroll
            for (int i2 = 0; i2 < 4; i2++) {
                int i = tid + i2 * 256;          // 1024 chunks per array
                int row = i >> 3, c8 = i & 7;
                cp16(st + arr * ARR_BYTES + row * (TSTRIDE * 2) + c8 * 16,
                     srcs[arr] + (size_t)(rbase + row) * CDIM + k0 + c8 * 8);
            }
        }
        cp_commit();
    };

    float acc[4][4][4];
    #pragma unroll
    for (int a = 0; a < 4; a++)
        #pragma unroll
        for (int b = 0; b < 4; b++)
            #pragma unroll
            for (int c = 0; c < 4; c++) acc[a][b][c] = 0.f;

    issue(0);
    for (int kt = 0; kt < 8; kt++) {
        if (kt < 7) { issue(kt + 1); cp_wait1(); } else { cp_wait0(); }
        __syncthreads();
        uint32_t st = sbase + (kt & 1) * STG_BYTES;

        #pragma unroll
        for (int ks = 0; ks < 4; ks++) {
            uint32_t a[4][2][4];
            #pragma unroll
            for (int mi = 0; mi < 4; mi++)
                #pragma unroll
                for (int s = 0; s < 2; s++) {
                    uint32_t ad = st + s * ARR_BYTES
                                + (wm + mi * 16 + rowA) * (TSTRIDE * 2)
                                + (ks * 16 + colA) * 2;
                    ldsm4(a[mi][s][0], a[mi][s][1], a[mi][s][2], a[mi][s][3], ad);
                }
            uint32_t bfr[2][2][4];
            #pragma unroll
            for (int p = 0; p < 2; p++)
                #pragma unroll
                for (int s = 0; s < 2; s++) {
                    uint32_t ad = st + (2 + s) * ARR_BYTES
                                + (wn + p * 16 + rowB) * (TSTRIDE * 2)
                                + (ks * 16 + colB) * 2;
                    ldsm4(bfr[p][s][0], bfr[p][s][1], bfr[p][s][2], bfr[p][s][3], ad);
                }
            #pragma unroll
            for (int mi = 0; mi < 4; mi++)
                #pragma unroll
                for (int ni = 0; ni < 4; ni++) {
                    int p = ni >> 1, h = (ni & 1) * 2;
                    mma16816(acc[mi][ni], a[mi][0], bfr[p][0][h], bfr[p][0][h + 1]); // hh
                    mma16816(acc[mi][ni], a[mi][0], bfr[p][1][h], bfr[p][1][h + 1]); // h*lo
                    mma16816(acc[mi][ni], a[mi][1], bfr[p][0][h], bfr[p][0][h + 1]); // lo*h
                }
        }
        __syncthreads();
    }

    // epilogue: bias, scale, split, store packed bf16x2
    #pragma unroll
    for (int mi = 0; mi < 4; mi++) {
        #pragma unroll
        for (int ni = 0; ni < 4; ni++) {
            int c = n0 + wn + ni * 8 + 2 * t4;
            float b0v = bias[c], b1v = bias[c + 1];
            #pragma unroll
            for (int rr = 0; rr < 2; rr++) {
                int r = m0 + wm + mi * 16 + gr + rr * 8;
                float v0 = (acc[mi][ni][rr * 2 + 0] + b0v) * scale;
                float v1 = (acc[mi][ni][rr * 2 + 1] + b1v) * scale;
                bf h0 = __float2bfloat16(v0), h1 = __float2bfloat16(v1);
                bf l0 = __float2bfloat16(v0 - __bfloat162float(h0));
                bf l1 = __float2bfloat16(v1 - __bfloat162float(h1));
                *reinterpret_cast<uint32_t*>(&outh[(size_t)r * CDIM + c]) = pack2(h0, h1);
                *reinterpret_cast<uint32_t*>(&outl[(size_t)r * CDIM + c]) = pack2(l0, l1);
            }
        }
    }
}

// ---------------------------------------------------------------------------
// Kernel 2: flash attention, P kept in registers, cp.async double-buffered
//   K/V, ldmatrix(+trans) fragment loads, fused transposed output.
//   grid (8 q-tiles, 64 groups), block 256 (8 warps x 16 q-rows)
// ---------------------------------------------------------------------------
__global__ __launch_bounds__(256, 1) void attn_kernel(float* __restrict__ out)
{
    extern __shared__ char smem[];
    const uint32_t sbase = (uint32_t)__cvta_generic_to_shared(smem);

    const int g  = blockIdx.y;
    const int qb = blockIdx.x;
    const int b  = g >> 3, gl = g & 7;

    const int tid = threadIdx.x, warp = tid >> 5, lane = tid & 31;
    const int gr = lane >> 2, t4 = lane & 3;
    const int j = lane >> 3, lr = lane & 7;
    const int rowA = (j & 1) * 8 + lr, colA = (j >> 1) * 8;   // A-frag / trans-V lane pattern
    const int rowB = (j >> 1) * 8 + lr, colB = (j & 1) * 8;   // B-frag (K) lane pattern

    const size_t gbase = (size_t)g * GROUP_ELEMS;
    const bf* kvsrc[4] = { g_Kh, g_Kl, g_Vh, g_Vl };

    // ---- prologue: Q into stage1 arrays {0,1}; KV(0) into stage0 ----
    {
        const bf* qsrc[2] = { g_Qh, g_Ql };
        #pragma unroll
        for (int s = 0; s < 2; s++)
            #pragma unroll
            for (int i2 = 0; i2 < 4; i2++) {
                int i = tid + i2 * 256;
                int row = i >> 3, c8 = i & 7;
                cp16(sbase + STG_BYTES + s * ARR_BYTES + row * (TSTRIDE * 2) + c8 * 16,
                     qsrc[s] + gbase + (size_t)qb * 8192 + row * 64 + c8 * 8);
            }
        cp_commit();
    }
    auto issue_kv = [&](int kt) {
        uint32_t st = sbase + (kt & 1) * STG_BYTES;
        #pragma unroll
        for (int arr = 0; arr < 4; arr++)
            #pragma unroll
            for (int i2 = 0; i2 < 4; i2++) {
                int i = tid + i2 * 256;
                int row = i >> 3, c8 = i & 7;
                cp16(st + arr * ARR_BYTES + row * (TSTRIDE * 2) + c8 * 16,
                     kvsrc[arr] + gbase + (size_t)kt * 8192 + row * 64 + c8 * 8);
            }
        cp_commit();
    };
    issue_kv(0);
    cp_wait1();          // Q group done
    __syncthreads();

    // ---- Q fragments ----
    uint32_t qa[4][2][4];
    #pragma unroll
    for (int ks = 0; ks < 4; ks++)
        #pragma unroll
        for (int s = 0; s < 2; s++) {
            uint32_t ad = sbase + STG_BYTES + s * ARR_BYTES
                        + (warp * 16 + rowA) * (TSTRIDE * 2) + (ks * 16 + colA) * 2;
            ldsm4(qa[ks][s][0], qa[ks][s][1], qa[ks][s][2], qa[ks][s][3], ad);
        }
    __syncthreads();     // stage1 may now be overwritten by KV(1)

    float mrow[2] = { -1e30f, -1e30f };
    float lrow[2] = { 0.f, 0.f };
    float o[8][4];
    #pragma unroll
    for (int i = 0; i < 8; i++)
        #pragma unroll
        for (int c = 0; c < 4; c++) o[i][c] = 0.f;

    for (int kt = 0; kt < 8; kt++) {
        if (kt < 7) { issue_kv(kt + 1); cp_wait1(); } else { cp_wait0(); }
        __syncthreads();
        uint32_t st = sbase + (kt & 1) * STG_BYTES;

        // ---- scores ----
        float sc[16][4];
        #pragma unroll
        for (int n2 = 0; n2 < 8; n2++) {
            float c0[4] = {0.f, 0.f, 0.f, 0.f};
            float c1[4] = {0.f, 0.f, 0.f, 0.f};
            #pragma unroll
            for (int ks = 0; ks < 4; ks++) {
                uint32_t kh0, kh1, kh2, kh3, kl0, kl1, kl2, kl3;
                uint32_t ah = st + 0 * ARR_BYTES + (n2 * 16 + rowB) * (TSTRIDE * 2) + (ks * 16 + colB) * 2;
                uint32_t al = st + 1 * ARR_BYTES + (n2 * 16 + rowB) * (TSTRIDE * 2) + (ks * 16 + colB) * 2;
                ldsm4(kh0, kh1, kh2, kh3, ah);
                ldsm4(kl0, kl1, kl2, kl3, al);
                mma16816(c0, qa[ks][0], kh0, kh1);
                mma16816(c0, qa[ks][0], kl0, kl1);
                mma16816(c0, qa[ks][1], kh0, kh1);
                mma16816(c1, qa[ks][0], kh2, kh3);
                mma16816(c1, qa[ks][0], kl2, kl3);
                mma16816(c1, qa[ks][1], kh2, kh3);
            }
            #pragma unroll
            for (int c = 0; c < 4; c++) { sc[2 * n2][c] = c0[c]; sc[2 * n2 + 1][c] = c1[c]; }
        }

        // ---- online softmax ----
        float tm0 = -1e30f, tm1 = -1e30f;
        #pragma unroll
        for (int ni = 0; ni < 16; ni++) {
            tm0 = fmaxf(tm0, fmaxf(sc[ni][0], sc[ni][1]));
            tm1 = fmaxf(tm1, fmaxf(sc[ni][2], sc[ni][3]));
        }
        tm0 = fmaxf(tm0, __shfl_xor_sync(0xffffffffu, tm0, 1));
        tm0 = fmaxf(tm0, __shfl_xor_sync(0xffffffffu, tm0, 2));
        tm1 = fmaxf(tm1, __shfl_xor_sync(0xffffffffu, tm1, 1));
        tm1 = fmaxf(tm1, __shfl_xor_sync(0xffffffffu, tm1, 2));
        float mn0 = fmaxf(mrow[0], tm0), mn1 = fmaxf(mrow[1], tm1);
        float alpha0 = __expf(mrow[0] - mn0), alpha1 = __expf(mrow[1] - mn1);

        // P stays in registers: C-fragment layout == A-fragment layout
        uint32_t phA[16], phB[16], plA[16], plB[16];
        float rs0 = 0.f, rs1 = 0.f;
        #pragma unroll
        for (int ni = 0; ni < 16; ni++) {
            float p0 = __expf(sc[ni][0] - mn0);
            float p1 = __expf(sc[ni][1] - mn0);
            float p2 = __expf(sc[ni][2] - mn1);
            float p3 = __expf(sc[ni][3] - mn1);
            rs0 += p0 + p1;  rs1 += p2 + p3;
            bf h0 = __float2bfloat16(p0), h1 = __float2bfloat16(p1);
            bf h2 = __float2bfloat16(p2), h3 = __float2bfloat16(p3);
            phA[ni] = pack2(h0, h1);
            phB[ni] = pack2(h2, h3);
            plA[ni] = pack2(__float2bfloat16(p0 - __bfloat162float(h0)),
                            __float2bfloat16(p1 - __bfloat162float(h1)));
            plB[ni] = pack2(__float2bfloat16(p2 - __bfloat162float(h2)),
                            __float2bfloat16(p3 - __bfloat162float(h3)));
        }
        rs0 += __shfl_xor_sync(0xffffffffu, rs0, 1);
        rs0 += __shfl_xor_sync(0xffffffffu, rs0, 2);
        rs1 += __shfl_xor_sync(0xffffffffu, rs1, 1);
        rs1 += __shfl_xor_sync(0xffffffffu, rs1, 2);
        lrow[0] = lrow[0] * alpha0 + rs0;
        lrow[1] = lrow[1] * alpha1 + rs1;
        mrow[0] = mn0; mrow[1] = mn1;
        #pragma unroll
        for (int i = 0; i < 8; i++) {
            o[i][0] *= alpha0; o[i][1] *= alpha0;
            o[i][2] *= alpha1; o[i][3] *= alpha1;
        }

        // ---- O += P @ V (V via ldmatrix.trans on [kv][d] tiles) ----
        #pragma unroll
        for (int ks = 0; ks < 8; ks++) {
            uint32_t ah[4] = { phA[2 * ks], phB[2 * ks], phA[2 * ks + 1], phB[2 * ks + 1] };
            uint32_t al[4] = { plA[2 * ks], plB[2 * ks], plA[2 * ks + 1], plB[2 * ks + 1] };
            #pragma unroll
            for (int n4 = 0; n4 < 4; n4++) {
                uint32_t vh0, vh1, vh2, vh3, vl0, vl1, vl2, vl3;
                uint32_t avh = st + 2 * ARR_BYTES + (ks * 16 + rowA) * (TSTRIDE * 2) + (n4 * 16 + colA) * 2;
                uint32_t avl = st + 3 * ARR_BYTES + (ks * 16 + rowA) * (TSTRIDE * 2) + (n4 * 16 + colA) * 2;
                ldsm4t(vh0, vh1, vh2, vh3, avh);
                ldsm4t(vl0, vl1, vl2, vl3, avl);
                mma16816(o[2 * n4],     ah, vh0, vh1);
                mma16816(o[2 * n4],     ah, vl0, vl1);
                mma16816(o[2 * n4],     al, vh0, vh1);
                mma16816(o[2 * n4 + 1], ah, vh2, vh3);
                mma16816(o[2 * n4 + 1], ah, vl2, vl3);
                mma16816(o[2 * n4 + 1], al, vh2, vh3);
            }
        }
        __syncthreads();
    }

    // ---- epilogue: normalize, stage in smem, write out transposed ----
    float* os = reinterpret_cast<float*>(smem);   // [128][65] fp32, reuses stage0
    float inv0 = 1.f / lrow[0], inv1 = 1.f / lrow[1];
    #pragma unroll
    for (int n2 = 0; n2 < 8; n2++) {
        int d = n2 * 8 + 2 * t4;
        int r = warp * 16 + gr;
        os[r * 65 + d]           = o[n2][0] * inv0;
        os[r * 65 + d + 1]       = o[n2][1] * inv0;
        os[(r + 8) * 65 + d]     = o[n2][2] * inv1;
        os[(r + 8) * 65 + d + 1] = o[n2][3] * inv1;
    }
    __syncthreads();

    // out[b][ch][p]: ch = (r%8)*64 + d, p = gl*128 + qb*16 + r/8
    float* ob = out + (size_t)b * CDIM * SDIM;
    #pragma unroll
    for (int it = 0; it < 32; it++) {
        int e = it * 256 + tid;
        int pl = e & 15, ch = e >> 4;
        int d = ch & 63, rm8 = ch >> 6;
        ob[(size_t)ch * SDIM + gl * 128 + qb * 16 + pl] = os[(pl * 8 + rm8) * 65 + d];
    }
}

// ---------------------------------------------------------------------------
// Launch
// ---------------------------------------------------------------------------
extern "C" void kernel_launch(void* const* d_in, const int* in_sizes, int n_in,
                              void* d_out, int out_size)
{
    (void)in_sizes; (void)n_in; (void)out_size;
    const float* x  = (const float*)d_in[0];
    const float* Wq = (const float*)d_in[1];
    const float* bq = (const float*)d_in[2];
    const float* Wk = (const float*)d_in[3];
    const float* bk = (const float*)d_in[4];
    const float* Wv = (const float*)d_in[5];
    const float* bv = (const float*)d_in[6];
    float* out = (float*)d_out;

    prep_x_kernel<<<dim3(CDIM / 32, SDIM / 32, BATCH), dim3(32, 8)>>>(x);
    prep_w_kernel<<<dim3(CDIM * CDIM / (256 * 4), 3), 256>>>(Wq, Wk, Wv);

    static int inited = 0;
    if (!inited) {
        cudaFuncSetAttribute(qkv_gemm_kernel, cudaFuncAttributeMaxDynamicSharedMemorySize, SMEM_TOT);
        cudaFuncSetAttribute(attn_kernel, cudaFuncAttributeMaxDynamicSharedMemorySize, SMEM_TOT);
        inited = 1;
    }

    qkv_gemm_kernel<<<dim3(CDIM / 128, MTOT / 128, 3), 256, SMEM_TOT>>>(bq, bk, bv);
    attn_kernel<<<dim3(SDIM / 128, NGROUPS), 256, SMEM_TOT>>>(out);
}

// round 4
// speedup vs baseline: 1.5219x; 1.0007x over previous
#include <cuda_runtime.h>
#include <cuda_bf16.h>
#include <cstdint>

typedef __nv_bfloat16 bf;

constexpr int BATCH = 8;
constexpr int CDIM  = 512;
constexpr int SDIM  = 1024;
constexpr int MTOT  = BATCH * SDIM;    // 8192
constexpr int HD    = 64;
constexpr int NGROUPS = 64;
constexpr int GROUP_ELEMS = SDIM * HD; // 65536

// bf16 hi/lo global scratch
__device__ bf g_Ah[MTOT * CDIM];
__device__ bf g_Al[MTOT * CDIM];
__device__ bf g_Wh[3 * CDIM * CDIM];
__device__ bf g_Wl[3 * CDIM * CDIM];
__device__ bf g_Qh[MTOT * CDIM];
__device__ bf g_Ql[MTOT * CDIM];
__device__ bf g_Kh[MTOT * CDIM];
__device__ bf g_Kl[MTOT * CDIM];
__device__ bf g_Vh[MTOT * CDIM];
__device__ bf g_Vl[MTOT * CDIM];

// ---------------------------------------------------------------------------
// helpers
// ---------------------------------------------------------------------------
__device__ __forceinline__ void mma16816(float c[4], const uint32_t a[4], uint32_t b0, uint32_t b1)
{
    asm volatile(
        "mma.sync.aligned.m16n8k16.row.col.f32.bf16.bf16.f32 "
        "{%0,%1,%2,%3}, {%4,%5,%6,%7}, {%8,%9}, {%0,%1,%2,%3};\n"
        : "+f"(c[0]), "+f"(c[1]), "+f"(c[2]), "+f"(c[3])
        : "r"(a[0]), "r"(a[1]), "r"(a[2]), "r"(a[3]), "r"(b0), "r"(b1));
}
__device__ __forceinline__ void ldsm4(uint32_t& r0, uint32_t& r1, uint32_t& r2, uint32_t& r3, uint32_t a)
{
    asm volatile("ldmatrix.sync.aligned.m8n8.x4.shared.b16 {%0,%1,%2,%3}, [%4];"
                 : "=r"(r0), "=r"(r1), "=r"(r2), "=r"(r3) : "r"(a));
}
__device__ __forceinline__ void ldsm4t(uint32_t& r0, uint32_t& r1, uint32_t& r2, uint32_t& r3, uint32_t a)
{
    asm volatile("ldmatrix.sync.aligned.m8n8.x4.trans.shared.b16 {%0,%1,%2,%3}, [%4];"
                 : "=r"(r0), "=r"(r1), "=r"(r2), "=r"(r3) : "r"(a));
}
__device__ __forceinline__ void cp16(uint32_t dst, const void* src)
{
    asm volatile("cp.async.cg.shared.global [%0], [%1], 16;" :: "r"(dst), "l"(src));
}
__device__ __forceinline__ void cp_commit() { asm volatile("cp.async.commit_group;"); }
__device__ __forceinline__ void cp_wait1()  { asm volatile("cp.async.wait_group 1;"); }
__device__ __forceinline__ void cp_wait0()  { asm volatile("cp.async.wait_group 0;"); }

__device__ __forceinline__ uint32_t pack2(bf a, bf b)
{
    __nv_bfloat162 t(a, b);
    return *reinterpret_cast<uint32_t*>(&t);
}

// smem tile geometry: rows of 64 bf16 padded to 72 elems (144 B, 16B aligned)
constexpr int TSTRIDE   = 72;
constexpr int ARR_BYTES = 128 * TSTRIDE * 2;     // 18432
constexpr int STG_BYTES = 4 * ARR_BYTES;         // 73728 (Kh,Kl,Vh,Vl) or (Ah,Al,Bh,Bl)
constexpr int SMEM_TOT  = 2 * STG_BYTES;         // 147456

// ---------------------------------------------------------------------------
// Prep kernels: fp32 -> bf16 hi/lo
// ---------------------------------------------------------------------------
__global__ void prep_x_kernel(const float* __restrict__ x)
{
    __shared__ float tile[32][33];
    const int b  = blockIdx.z;
    const int c0 = blockIdx.x * 32;
    const int p0 = blockIdx.y * 32;
    const int tx = threadIdx.x, ty = threadIdx.y;
    #pragma unroll
    for (int i = 0; i < 32; i += 8)
        tile[ty + i][tx] = x[((size_t)b * CDIM + c0 + ty + i) * SDIM + p0 + tx];
    __syncthreads();
    #pragma unroll
    for (int i = 0; i < 32; i += 8) {
        int s = b * SDIM + p0 + ty + i;
        int c = c0 + tx;
        float v = tile[tx][ty + i];
        bf h = __float2bfloat16(v);
        g_Ah[(size_t)s * CDIM + c] = h;
        g_Al[(size_t)s * CDIM + c] = __float2bfloat16(v - __bfloat162float(h));
    }
}

__global__ void prep_w_kernel(const float* __restrict__ Wq,
                              const float* __restrict__ Wk,
                              const float* __restrict__ Wv)
{
    const int mat = blockIdx.y;
    const float* W = (mat == 0) ? Wq : (mat == 1) ? Wk : Wv;
    int base = (blockIdx.x * 256 + threadIdx.x) * 4;
    size_t o = (size_t)mat * CDIM * CDIM;
    #pragma unroll
    for (int e = 0; e < 4; e++) {
        float v = W[base + e];
        bf h = __float2bfloat16(v);
        g_Wh[o + base + e] = h;
        g_Wl[o + base + e] = __float2bfloat16(v - __bfloat162float(h));
    }
}

// ---------------------------------------------------------------------------
// Kernel 1: QKV GEMM, pure bf16, cp.async double buffered, ldmatrix frags.
//   grid (4, 64, 3), block 256 (8 warps, 2x4 layout, 64x32 warp tiles)
//   Epilogue writes bf16 hi/lo (Q scaled by 0.125).
// ---------------------------------------------------------------------------
__global__ __launch_bounds__(256, 1) void qkv_gemm_kernel(
    const float* __restrict__ bq, const float* __restrict__ bk, const float* __restrict__ bv)
{
    extern __shared__ char smem[];
    const uint32_t sbase = (uint32_t)__cvta_generic_to_shared(smem);

    const int mat = blockIdx.z;
    const float* bias = (mat == 0) ? bq : (mat == 1) ? bk : bv;
    const float scale = (mat == 0) ? 0.125f : 1.0f;
    bf* outh = (mat == 0) ? g_Qh : (mat == 1) ? g_Kh : g_Vh;
    bf* outl = (mat == 0) ? g_Ql : (mat == 1) ? g_Kl : g_Vl;

    const int m0 = blockIdx.y * 128;
    const int n0 = blockIdx.x * 128;
    const int tid = threadIdx.x, warp = tid >> 5, lane = tid & 31;
    const int wm = (warp >> 2) * 64, wn = (warp & 3) * 32;
    const int gr = lane >> 2, t4 = lane & 3;
    const int j = lane >> 3, lr = lane & 7;
    const int rowA = (j & 1) * 8 + lr, colA = (j >> 1) * 8;   // A-frag lane pattern
    const int rowB = (j >> 1) * 8 + lr, colB = (j & 1) * 8;   // B-frag lane pattern

    const bf* srcs[4] = { g_Ah, g_Al, g_Wh + (size_t)mat * CDIM * CDIM, g_Wl + (size_t)mat * CDIM * CDIM };

    auto issue = [&](int kt) {
        int k0 = kt * 64;
        uint32_t st = sbase + (kt & 1) * STG_BYTES;
        #pragma unroll
        for (int arr = 0; arr < 4; arr++) {
            int rbase = (arr < 2) ? m0 : n0;
            #pragma unroll
            for (int i2 = 0; i2 < 4; i2++) {
                int i = tid + i2 * 256;          // 1024 chunks per array
                int row = i >> 3, c8 = i & 7;
                cp16(st + arr * ARR_BYTES + row * (TSTRIDE * 2) + c8 * 16,
                     srcs[arr] + (size_t)(rbase + row) * CDIM + k0 + c8 * 8);
            }
        }
        cp_commit();
    };

    float acc[4][4][4];
    #pragma unroll
    for (int a = 0; a < 4; a++)
        #pragma unroll
        for (int b = 0; b < 4; b++)
            #pragma unroll
            for (int c = 0; c < 4; c++) acc[a][b][c] = 0.f;

    issue(0);
    for (int kt = 0; kt < 8; kt++) {
        if (kt < 7) { issue(kt + 1); cp_wait1(); } else { cp_wait0(); }
        __syncthreads();
        uint32_t st = sbase + (kt & 1) * STG_BYTES;

        #pragma unroll
        for (int ks = 0; ks < 4; ks++) {
            uint32_t a[4][2][4];
            #pragma unroll
            for (int mi = 0; mi < 4; mi++)
                #pragma unroll
                for (int s = 0; s < 2; s++) {
                    uint32_t ad = st + s * ARR_BYTES
                                + (wm + mi * 16 + rowA) * (TSTRIDE * 2)
                                + (ks * 16 + colA) * 2;
                    ldsm4(a[mi][s][0], a[mi][s][1], a[mi][s][2], a[mi][s][3], ad);
                }
            uint32_t bfr[2][2][4];
            #pragma unroll
            for (int p = 0; p < 2; p++)
                #pragma unroll
                for (int s = 0; s < 2; s++) {
                    uint32_t ad = st + (2 + s) * ARR_BYTES
                                + (wn + p * 16 + rowB) * (TSTRIDE * 2)
                                + (ks * 16 + colB) * 2;
                    ldsm4(bfr[p][s][0], bfr[p][s][1], bfr[p][s][2], bfr[p][s][3], ad);
                }
            #pragma unroll
            for (int mi = 0; mi < 4; mi++)
                #pragma unroll
                for (int ni = 0; ni < 4; ni++) {
                    int p = ni >> 1, h = (ni & 1) * 2;
                    mma16816(acc[mi][ni], a[mi][0], bfr[p][0][h], bfr[p][0][h + 1]); // hh
                    mma16816(acc[mi][ni], a[mi][0], bfr[p][1][h], bfr[p][1][h + 1]); // h*lo
                    mma16816(acc[mi][ni], a[mi][1], bfr[p][0][h], bfr[p][0][h + 1]); // lo*h
                }
        }
        __syncthreads();
    }

    // epilogue: bias, scale, split, store packed bf16x2
    #pragma unroll
    for (int mi = 0; mi < 4; mi++) {
        #pragma unroll
        for (int ni = 0; ni < 4; ni++) {
            int c = n0 + wn + ni * 8 + 2 * t4;
            float b0v = bias[c], b1v = bias[c + 1];
            #pragma unroll
            for (int rr = 0; rr < 2; rr++) {
                int r = m0 + wm + mi * 16 + gr + rr * 8;
                float v0 = (acc[mi][ni][rr * 2 + 0] + b0v) * scale;
                float v1 = (acc[mi][ni][rr * 2 + 1] + b1v) * scale;
                bf h0 = __float2bfloat16(v0), h1 = __float2bfloat16(v1);
                bf l0 = __float2bfloat16(v0 - __bfloat162float(h0));
                bf l1 = __float2bfloat16(v1 - __bfloat162float(h1));
                *reinterpret_cast<uint32_t*>(&outh[(size_t)r * CDIM + c]) = pack2(h0, h1);
                *reinterpret_cast<uint32_t*>(&outl[(size_t)r * CDIM + c]) = pack2(l0, l1);
            }
        }
    }
}

// ---------------------------------------------------------------------------
// Kernel 2: flash attention, P kept in registers, cp.async double-buffered
//   K/V, ldmatrix(+trans) fragment loads, fused transposed output.
//   grid (8 q-tiles, 64 groups), block 256 (8 warps x 16 q-rows)
// ---------------------------------------------------------------------------
__global__ __launch_bounds__(256, 1) void attn_kernel(float* __restrict__ out)
{
    extern __shared__ char smem[];
    const uint32_t sbase = (uint32_t)__cvta_generic_to_shared(smem);

    const int g  = blockIdx.y;
    const int qb = blockIdx.x;
    const int b  = g >> 3, gl = g & 7;

    const int tid = threadIdx.x, warp = tid >> 5, lane = tid & 31;
    const int gr = lane >> 2, t4 = lane & 3;
    const int j = lane >> 3, lr = lane & 7;
    const int rowA = (j & 1) * 8 + lr, colA = (j >> 1) * 8;   // A-frag / trans-V lane pattern
    const int rowB = (j >> 1) * 8 + lr, colB = (j & 1) * 8;   // B-frag (K) lane pattern

    const size_t gbase = (size_t)g * GROUP_ELEMS;
    const bf* kvsrc[4] = { g_Kh, g_Kl, g_Vh, g_Vl };

    // ---- prologue: Q into stage1 arrays {0,1}; KV(0) into stage0 ----
    {
        const bf* qsrc[2] = { g_Qh, g_Ql };
        #pragma unroll
        for (int s = 0; s < 2; s++)
            #pragma unroll
            for (int i2 = 0; i2 < 4; i2++) {
                int i = tid + i2 * 256;
                int row = i >> 3, c8 = i & 7;
                cp16(sbase + STG_BYTES + s * ARR_BYTES + row * (TSTRIDE * 2) + c8 * 16,
                     qsrc[s] + gbase + (size_t)qb * 8192 + row * 64 + c8 * 8);
            }
        cp_commit();
    }
    auto issue_kv = [&](int kt) {
        uint32_t st = sbase + (kt & 1) * STG_BYTES;
        #pragma unroll
        for (int arr = 0; arr < 4; arr++)
            #pragma unroll
            for (int i2 = 0; i2 < 4; i2++) {
                int i = tid + i2 * 256;
                int row = i >> 3, c8 = i & 7;
                cp16(st + arr * ARR_BYTES + row * (TSTRIDE * 2) + c8 * 16,
                     kvsrc[arr] + gbase + (size_t)kt * 8192 + row * 64 + c8 * 8);
            }
        cp_commit();
    };
    issue_kv(0);
    cp_wait1();          // Q group done
    __syncthreads();

    // ---- Q fragments ----
    uint32_t qa[4][2][4];
    #pragma unroll
    for (int ks = 0; ks < 4; ks++)
        #pragma unroll
        for (int s = 0; s < 2; s++) {
            uint32_t ad = sbase + STG_BYTES + s * ARR_BYTES
                        + (warp * 16 + rowA) * (TSTRIDE * 2) + (ks * 16 + colA) * 2;
            ldsm4(qa[ks][s][0], qa[ks][s][1], qa[ks][s][2], qa[ks][s][3], ad);
        }
    __syncthreads();     // stage1 may now be overwritten by KV(1)

    float mrow[2] = { -1e30f, -1e30f };
    float lrow[2] = { 0.f, 0.f };
    float o[8][4];
    #pragma unroll
    for (int i = 0; i < 8; i++)
        #pragma unroll
        for (int c = 0; c < 4; c++) o[i][c] = 0.f;

    for (int kt = 0; kt < 8; kt++) {
        if (kt < 7) { issue_kv(kt + 1); cp_wait1(); } else { cp_wait0(); }
        __syncthreads();
        uint32_t st = sbase + (kt & 1) * STG_BYTES;

        // ---- scores ----
        float sc[16][4];
        #pragma unroll
        for (int n2 = 0; n2 < 8; n2++) {
            float c0[4] = {0.f, 0.f, 0.f, 0.f};
            float c1[4] = {0.f, 0.f, 0.f, 0.f};
            #pragma unroll
            for (int ks = 0; ks < 4; ks++) {
                uint32_t kh0, kh1, kh2, kh3, kl0, kl1, kl2, kl3;
                uint32_t ah = st + 0 * ARR_BYTES + (n2 * 16 + rowB) * (TSTRIDE * 2) + (ks * 16 + colB) * 2;
                uint32_t al = st + 1 * ARR_BYTES + (n2 * 16 + rowB) * (TSTRIDE * 2) + (ks * 16 + colB) * 2;
                ldsm4(kh0, kh1, kh2, kh3, ah);
                ldsm4(kl0, kl1, kl2, kl3, al);
                mma16816(c0, qa[ks][0], kh0, kh1);
                mma16816(c0, qa[ks][0], kl0, kl1);
                mma16816(c0, qa[ks][1], kh0, kh1);
                mma16816(c1, qa[ks][0], kh2, kh3);
                mma16816(c1, qa[ks][0], kl2, kl3);
                mma16816(c1, qa[ks][1], kh2, kh3);
            }
            #pragma unroll
            for (int c = 0; c < 4; c++) { sc[2 * n2][c] = c0[c]; sc[2 * n2 + 1][c] = c1[c]; }
        }

        // ---- online softmax ----
        float tm0 = -1e30f, tm1 = -1e30f;
        #pragma unroll
        for (int ni = 0; ni < 16; ni++) {
            tm0 = fmaxf(tm0, fmaxf(sc[ni][0], sc[ni][1]));
            tm1 = fmaxf(tm1, fmaxf(sc[ni][2], sc[ni][3]));
        }
        tm0 = fmaxf(tm0, __shfl_xor_sync(0xffffffffu, tm0, 1));
        tm0 = fmaxf(tm0, __shfl_xor_sync(0xffffffffu, tm0, 2));
        tm1 = fmaxf(tm1, __shfl_xor_sync(0xffffffffu, tm1, 1));
        tm1 = fmaxf(tm1, __shfl_xor_sync(0xffffffffu, tm1, 2));
        float mn0 = fmaxf(mrow[0], tm0), mn1 = fmaxf(mrow[1], tm1);
        float alpha0 = __expf(mrow[0] - mn0), alpha1 = __expf(mrow[1] - mn1);

        // P stays in registers: C-fragment layout == A-fragment layout
        uint32_t phA[16], phB[16], plA[16], plB[16];
        float rs0 = 0.f, rs1 = 0.f;
        #pragma unroll
        for (int ni = 0; ni < 16; ni++) {
            float p0 = __expf(sc[ni][0] - mn0);
            float p1 = __expf(sc[ni][1] - mn0);
            float p2 = __expf(sc[ni][2] - mn1);
            float p3 = __expf(sc[ni][3] - mn1);
            rs0 += p0 + p1;  rs1 += p2 + p3;
            bf h0 = __float2bfloat16(p0), h1 = __float2bfloat16(p1);
            bf h2 = __float2bfloat16(p2), h3 = __float2bfloat16(p3);
            phA[ni] = pack2(h0, h1);
            phB[ni] = pack2(h2, h3);
            plA[ni] = pack2(__float2bfloat16(p0 - __bfloat162float(h0)),
                            __float2bfloat16(p1 - __bfloat162float(h1)));
            plB[ni] = pack2(__float2bfloat16(p2 - __bfloat162float(h2)),
                            __float2bfloat16(p3 - __bfloat162float(h3)));
        }
        rs0 += __shfl_xor_sync(0xffffffffu, rs0, 1);
        rs0 += __shfl_xor_sync(0xffffffffu, rs0, 2);
        rs1 += __shfl_xor_sync(0xffffffffu, rs1, 1);
        rs1 += __shfl_xor_sync(0xffffffffu, rs1, 2);
        lrow[0] = lrow[0] * alpha0 + rs0;
        lrow[1] = lrow[1] * alpha1 + rs1;
        mrow[0] = mn0; mrow[1] = mn1;
        #pragma unroll
        for (int i = 0; i < 8; i++) {
            o[i][0] *= alpha0; o[i][1] *= alpha0;
            o[i][2] *= alpha1; o[i][3] *= alpha1;
        }

        // ---- O += P @ V (V via ldmatrix.trans on [kv][d] tiles) ----
        #pragma unroll
        for (int ks = 0; ks < 8; ks++) {
            uint32_t ah[4] = { phA[2 * ks], phB[2 * ks], phA[2 * ks + 1], phB[2 * ks + 1] };
            uint32_t al[4] = { plA[2 * ks], plB[2 * ks], plA[2 * ks + 1], plB[2 * ks + 1] };
            #pragma unroll
            for (int n4 = 0; n4 < 4; n4++) {
                uint32_t vh0, vh1, vh2, vh3, vl0, vl1, vl2, vl3;
                uint32_t avh = st + 2 * ARR_BYTES + (ks * 16 + rowA) * (TSTRIDE * 2) + (n4 * 16 + colA) * 2;
                uint32_t avl = st + 3 * ARR_BYTES + (ks * 16 + rowA) * (TSTRIDE * 2) + (n4 * 16 + colA) * 2;
                ldsm4t(vh0, vh1, vh2, vh3, avh);
                ldsm4t(vl0, vl1, vl2, vl3, avl);
                mma16816(o[2 * n4],     ah, vh0, vh1);
                mma16816(o[2 * n4],     ah, vl0, vl1);
                mma16816(o[2 * n4],     al, vh0, vh1);
                mma16816(o[2 * n4 + 1], ah, vh2, vh3);
                mma16816(o[2 * n4 + 1], ah, vl2, vl3);
                mma16816(o[2 * n4 + 1], al, vh2, vh3);
            }
        }
        __syncthreads();
    }

    // ---- epilogue: normalize, stage in smem, write out transposed ----
    float* os = reinterpret_cast<float*>(smem);   // [128][65] fp32, reuses stage0
    float inv0 = 1.f / lrow[0], inv1 = 1.f / lrow[1];
    #pragma unroll
    for (int n2 = 0; n2 < 8; n2++) {
        int d = n2 * 8 + 2 * t4;
        int r = warp * 16 + gr;
        os[r * 65 + d]           = o[n2][0] * inv0;
        os[r * 65 + d + 1]       = o[n2][1] * inv0;
        os[(r + 8) * 65 + d]     = o[n2][2] * inv1;
        os[(r + 8) * 65 + d + 1] = o[n2][3] * inv1;
    }
    __syncthreads();

    // out[b][ch][p]: ch = (r%8)*64 + d, p = gl*128 + qb*16 + r/8
    float* ob = out + (size_t)b * CDIM * SDIM;
    #pragma unroll
    for (int it = 0; it < 32; it++) {
        int e = it * 256 + tid;
        int pl = e & 15, ch = e >> 4;
        int d = ch & 63, rm8 = ch >> 6;
        ob[(size_t)ch * SDIM + gl * 128 + qb * 16 + pl] = os[(pl * 8 + rm8) * 65 + d];
    }
}

// ---------------------------------------------------------------------------
// Launch
// ---------------------------------------------------------------------------
extern "C" void kernel_launch(void* const* d_in, const int* in_sizes, int n_in,
                              void* d_out, int out_size)
{
    (void)in_sizes; (void)n_in; (void)out_size;
    const float* x  = (const float*)d_in[0];
    const float* Wq = (const float*)d_in[1];
    const float* bq = (const float*)d_in[2];
    const float* Wk = (const float*)d_in[3];
    const float* bk = (const float*)d_in[4];
    const float* Wv = (const float*)d_in[5];
    const float* bv = (const float*)d_in[6];
    float* out = (float*)d_out;

    prep_x_kernel<<<dim3(CDIM / 32, SDIM / 32, BATCH), dim3(32, 8)>>>(x);
    prep_w_kernel<<<dim3(CDIM * CDIM / (256 * 4), 3), 256>>>(Wq, Wk, Wv);

    static int inited = 0;
    if (!inited) {
        cudaFuncSetAttribute(qkv_gemm_kernel, cudaFuncAttributeMaxDynamicSharedMemorySize, SMEM_TOT);
        cudaFuncSetAttribute(attn_kernel, cudaFuncAttributeMaxDynamicSharedMemorySize, SMEM_TOT);
        inited = 1;
    }

    qkv_gemm_kernel<<<dim3(CDIM / 128, MTOT / 128, 3), 256, SMEM_TOT>>>(bq, bk, bv);
    attn_kernel<<<dim3(SDIM / 128, NGROUPS), 256, SMEM_TOT>>>(out);
}